// round 2
// baseline (speedup 1.0000x reference)
#include <cuda_runtime.h>
#include <cuda_bf16.h>

#define VOCAB  20000
#define TOPK   8
#define GLOVE  300
#define OUTC   100
#define NLAB   8
#define ROWS   16
#define NTOK   4096
#define FACT_PER_V (TOPK * 2 * GLOVE)   // 4800 floats
#define C4     75                        // GLOVE/4 float4s per row

// Static scratch (no allocation allowed)
__device__ float g_S[VOCAB * GLOVE];     // per-vocab row-sum (24 MB)
__device__ float g_T[NTOK * GLOVE];      // per-token label-sum (4.9 MB)
__device__ float g_wt[GLOVE * OUTC];     // W transposed: Wt[c*100 + o]
__device__ int   g_used[VOCAB];

// ---------------------------------------------------------------------------
// K0: clear usage flags + transpose W
// ---------------------------------------------------------------------------
__global__ void k_clear_wt(const float* __restrict__ W) {
    int i = blockIdx.x * blockDim.x + threadIdx.x;
    if (i < VOCAB) g_used[i] = 0;
    if (i < GLOVE * OUTC) {
        int c = i / OUTC, o = i % OUTC;
        g_wt[i] = W[o * GLOVE + c];
    }
}

// ---------------------------------------------------------------------------
// K1: mark used vocab entries (benign races)
// ---------------------------------------------------------------------------
__global__ void k_mark(const int* __restrict__ labels, int n) {
    int i = blockIdx.x * blockDim.x + threadIdx.x;
    if (i < n) g_used[labels[i]] = 1;
}

// ---------------------------------------------------------------------------
// K2 (HBM-bound): warp-per-vocab row-sum, float4.
// Lane l owns float4 columns {l, l+32, l+64} (c < 75); sums 16 rows each.
// Per-row warp access = 32 x 16B = 512B contiguous. ~310 MB streamed once.
// ---------------------------------------------------------------------------
__global__ __launch_bounds__(256) void k_rowsum(const float* __restrict__ fact) {
    const int gw   = (blockIdx.x * blockDim.x + threadIdx.x) >> 5;
    const int lane = threadIdx.x & 31;
    if (gw >= VOCAB) return;
    if (!g_used[gw]) return;

    const float4* __restrict__ f4 = (const float4*)(fact + (size_t)gw * FACT_PER_V);
    float4* __restrict__ s4 = (float4*)(g_S + (size_t)gw * GLOVE);

    #pragma unroll
    for (int cb = 0; cb < 3; cb++) {
        const int c = lane + cb * 32;
        if (c < C4) {
            float4 acc = make_float4(0.f, 0.f, 0.f, 0.f);
            #pragma unroll
            for (int r = 0; r < ROWS; r++) {
                float4 x = f4[r * C4 + c];
                acc.x += x.x; acc.y += x.y; acc.z += x.z; acc.w += x.w;
            }
            s4[c] = acc;
        }
    }
}

// ---------------------------------------------------------------------------
// K3 (L2-hot): warp-per-token, T[token] = sum_{8 labels} S[label]
// ---------------------------------------------------------------------------
__global__ __launch_bounds__(256) void k_gather(const int* __restrict__ labels) {
    const int gw   = (blockIdx.x * blockDim.x + threadIdx.x) >> 5;
    const int lane = threadIdx.x & 31;
    if (gw >= NTOK) return;

    int lab[NLAB];
    #pragma unroll
    for (int j = 0; j < NLAB; j++) lab[j] = labels[gw * NLAB + j];   // broadcast

    const float4* __restrict__ S4 = (const float4*)g_S;
    float4* __restrict__ T4 = (float4*)(g_T + (size_t)gw * GLOVE);

    #pragma unroll
    for (int cb = 0; cb < 3; cb++) {
        const int c = lane + cb * 32;
        if (c < C4) {
            float4 acc = make_float4(0.f, 0.f, 0.f, 0.f);
            #pragma unroll
            for (int j = 0; j < NLAB; j++) {
                float4 x = S4[(size_t)lab[j] * C4 + c];
                acc.x += x.x; acc.y += x.y; acc.z += x.z; acc.w += x.w;
            }
            T4[c] = acc;
        }
    }
}

// ---------------------------------------------------------------------------
// K4 (fma-bound): out[4096,100] = T @ Wt * (1/128) + bias
// Thread tile: 4 tokens x 4 outputs. 200 threads = 8 token-groups x 25 o-groups.
// Weights read as float4, L1-resident; T reads broadcast within lane groups.
// ---------------------------------------------------------------------------
__global__ __launch_bounds__(200) void k_gemm(const float* __restrict__ bias,
                                              float* __restrict__ out) {
    const int tid = threadIdx.x;
    const int o4  = tid % 25;                      // output group (4 outs)
    const int tg  = blockIdx.x * 8 + tid / 25;     // token group (4 tokens)
    const int tok0 = tg * 4;

    const float*  __restrict__ T0 = g_T + (size_t)tok0 * GLOVE;
    const float4* __restrict__ W4 = (const float4*)g_wt;   // [300][25] float4

    float4 a0 = make_float4(0,0,0,0), a1 = a0, a2 = a0, a3 = a0;

    #pragma unroll 4
    for (int k = 0; k < GLOVE; k++) {
        float4 w = W4[k * 25 + o4];
        float t0 = T0[k];
        float t1 = T0[GLOVE + k];
        float t2 = T0[2 * GLOVE + k];
        float t3 = T0[3 * GLOVE + k];
        a0.x += w.x * t0; a0.y += w.y * t0; a0.z += w.z * t0; a0.w += w.w * t0;
        a1.x += w.x * t1; a1.y += w.y * t1; a1.z += w.z * t1; a1.w += w.w * t1;
        a2.x += w.x * t2; a2.y += w.y * t2; a2.z += w.z * t2; a2.w += w.w * t2;
        a3.x += w.x * t3; a3.y += w.y * t3; a3.z += w.z * t3; a3.w += w.w * t3;
    }

    const float sc = 1.0f / (NLAB * ROWS);
    float4 b4 = ((const float4*)bias)[o4];
    float4* __restrict__ out4 = (float4*)out;
    float4 r;
    r.x = a0.x * sc + b4.x; r.y = a0.y * sc + b4.y; r.z = a0.z * sc + b4.z; r.w = a0.w * sc + b4.w;
    out4[(size_t)(tok0 + 0) * 25 + o4] = r;
    r.x = a1.x * sc + b4.x; r.y = a1.y * sc + b4.y; r.z = a1.z * sc + b4.z; r.w = a1.w * sc + b4.w;
    out4[(size_t)(tok0 + 1) * 25 + o4] = r;
    r.x = a2.x * sc + b4.x; r.y = a2.y * sc + b4.y; r.z = a2.z * sc + b4.z; r.w = a2.w * sc + b4.w;
    out4[(size_t)(tok0 + 2) * 25 + o4] = r;
    r.x = a3.x * sc + b4.x; r.y = a3.y * sc + b4.y; r.z = a3.z * sc + b4.z; r.w = a3.w * sc + b4.w;
    out4[(size_t)(tok0 + 3) * 25 + o4] = r;
}

// ---------------------------------------------------------------------------
extern "C" void kernel_launch(void* const* d_in, const int* in_sizes, int n_in,
                              void* d_out, int out_size) {
    const int*   labels = (const int*)d_in[0];    // [32,128,8] int32
    const float* fact   = (const float*)d_in[1];  // [20000,8,600] f32
    const float* W      = (const float*)d_in[2];  // [100,300] f32
    const float* bias   = (const float*)d_in[3];  // [100] f32
    float* out = (float*)d_out;                   // [32,128,100] f32

    const int n_labels_total = in_sizes[0];       // 32768

    k_clear_wt<<<(GLOVE * OUTC + 255) / 256, 256>>>(W);
    k_mark<<<(n_labels_total + 255) / 256, 256>>>(labels, n_labels_total);
    k_rowsum<<<(VOCAB * 32 + 255) / 256, 256>>>(fact);   // warp per vocab entry
    k_gather<<<(NTOK * 32 + 255) / 256, 256>>>(labels);  // warp per token
    k_gemm<<<NTOK / 32, 200>>>(bias, out);               // 128 blocks
}